// round 17
// baseline (speedup 1.0000x reference)
#include <cuda_runtime.h>
#include <cstdint>

// ---------------------------------------------------------------------------
// GCNNet fused single-kernel implementation.
// An = D^-1/2 (A+I) D^-1/2, A = (mean_bands(graph) != 0). Dense pattern
// (measure-1 for Gaussian graph) => An = (1/30)*J (rank-1):
//   h1 = relu((1/30) colsum(real) @ W1 + b1)      (all rows identical)
//   h2 = relu(h1 @ W2 + b2)                       (An row-sums == 1)
//   x  = relu(h2 . Wlin + blin); out[c] = x * rowsum(Wconv[c]) + bconv[c]
// Shape: TB=2 batches/block, 128 threads, grid 2048, 8 blocks/SM (RF cap).
// Finer block granularity keeps every SM at its full block cap and halves
// tail imbalance. Each of the 4 warps streams HALF the rows (15) of one
// batch; k-major smem holds 4 partial colsums per k (b0h0,b0h1,b1h0,b1h1)
// and the FFMA2 loop packs halves as f32x2 pairs — identical loop body,
// the h0+h1 combine folds into the existing linear reduction.
// ---------------------------------------------------------------------------

#define B_TOT   4096
#define BANDS   5
#define NN      30
#define IN_C    512
#define FF      128
#define CC      9
#define TB      2             // batches per block
#define SB      6             // padded slot stride (floats) in k-major smem

typedef unsigned long long u64t;

// ---- f32x2 helpers --------------------------------------------------------
__device__ __forceinline__ u64t pk2(float lo, float hi) {
    u64t r; asm("mov.b64 %0,{%1,%2};" : "=l"(r) : "f"(lo), "f"(hi)); return r;
}
__device__ __forceinline__ void upk2(float& lo, float& hi, u64t v) {
    asm("mov.b64 {%0,%1},%2;" : "=f"(lo), "=f"(hi) : "l"(v));
}
__device__ __forceinline__ void fma2(u64t& d, u64t a, u64t b) {
    asm("fma.rn.f32x2 %0,%1,%2,%0;" : "+l"(d) : "l"(a), "l"(b));
}

// global scratch for the (never-taken-in-practice) honest fallback path.
__device__ float g_fbscratch[B_TOT / TB][9216];

// ---------------------------------------------------------------------------
// graph density flags for this block's TB batches (128 threads).
// ---------------------------------------------------------------------------
__device__ __forceinline__ void flags_check(
    int b0, int tid, const float* __restrict__ graph, int* flagS)
{
    for (int i = tid; i < TB * 225; i += 128) {
        int b = i / 225, idx = i - b * 225;
        const float4* g4 = (const float4*)(graph + (size_t)(b0 + b) * (BANDS * NN * NN));
        float4 a0 = g4[idx];
        float4 a1 = g4[225 + idx];
        float4 a2 = g4[450 + idx];
        float4 a3 = g4[675 + idx];
        float4 a4 = g4[900 + idx];
        float s[4];
        s[0] = a0.x + a1.x + a2.x + a3.x + a4.x;
        s[1] = a0.y + a1.y + a2.y + a3.y + a4.y;
        s[2] = a0.z + a1.z + a2.z + a3.z + a4.z;
        s[3] = a0.w + a1.w + a2.w + a3.w + a4.w;
        bool bad = false;
        #pragma unroll
        for (int j = 0; j < 4; j++) {
            int p = idx * 4 + j;
            int n = p / NN, m = p - n * NN;
            if (n != m && s[j] * 0.2f == 0.0f) bad = true;
        }
        if (bad) flagS[b] = 0;
    }
}

// ---------------------------------------------------------------------------
// honest fallback for one non-dense batch; 128 threads, global scratch.
// ---------------------------------------------------------------------------
__device__ void fallback_batch(
    int b, float* S, int tid,
    const float* __restrict__ real, const float* __restrict__ graph,
    const float* __restrict__ W1, const float* __restrict__ b1,
    const float* __restrict__ W2, const float* __restrict__ b2,
    const float* __restrict__ Wlin, const float* __restrict__ blin,
    const float* __restrict__ Wconv, const float* __restrict__ bconv,
    float* __restrict__ out)
{
    float* An   = S;                    // 900 (pad to 960 incl. dinv)
    float* dinv = S + 900;              // 30
    float* Ys   = S + 960;              // 3840
    float* Hs   = Ys + 3840;            // 3840
    float* rrow = Hs + 3840;            // 512
    float* xsb  = rrow + 512;           // 30

    const float* g = graph + (size_t)b * (BANDS * NN * NN);
    for (int p = tid; p < NN * NN; p += 128) {
        int n = p / NN, m = p - n * NN;
        float s5 = g[p] + g[900 + p] + g[1800 + p] + g[2700 + p] + g[3600 + p];
        float a = (s5 * 0.2f != 0.0f) ? 1.0f : 0.0f;
        if (n == m) a = 1.0f;
        An[p] = a;
    }
    __syncthreads();
    if (tid < NN) {
        float dg = 0.f;
        for (int m = 0; m < NN; m++) dg += An[tid * NN + m];
        dinv[tid] = (dg > 0.f) ? rsqrtf(dg) : 0.0f;
    }
    __syncthreads();
    for (int p = tid; p < NN * NN; p += 128) {
        int n = p / NN, m = p - n * NN;
        An[p] = dinv[n] * An[p] * dinv[m];
    }
    __syncthreads();

    const float* rb = real + (size_t)b * NN * IN_C;
    for (int n = 0; n < NN; n++) {
        for (int c = tid; c < IN_C; c += 128) rrow[c] = rb[n * IN_C + c];
        __syncthreads();
        {
            float accv = 0.f;
            for (int c = 0; c < IN_C; c++) accv += rrow[c] * W1[c * FF + tid];
            Ys[n * FF + tid] = accv;
        }
        __syncthreads();
    }
    {
        float bb = b1[tid];
        for (int n = 0; n < NN; n++) {
            float accv = 0.f;
            for (int m = 0; m < NN; m++) accv += An[n * NN + m] * Ys[m * FF + tid];
            Hs[n * FF + tid] = fmaxf(accv + bb, 0.0f);
        }
    }
    __syncthreads();
    for (int n = 0; n < NN; n++) {
        float accv = 0.f;
        for (int c = 0; c < FF; c++) accv += Hs[n * FF + c] * W2[c * FF + tid];
        Ys[n * FF + tid] = accv;
    }
    __syncthreads();
    {
        float bb = b2[tid];
        for (int n = 0; n < NN; n++) {
            float accv = 0.f;
            for (int m = 0; m < NN; m++) accv += An[n * NN + m] * Ys[m * FF + tid];
            Hs[n * FF + tid] = fmaxf(accv + bb, 0.0f);
        }
    }
    __syncthreads();
    if (tid < NN) {
        float accv = 0.f;
        for (int ff = 0; ff < FF; ff++) accv += Hs[tid * FF + ff] * Wlin[ff];
        xsb[tid] = fmaxf(accv + blin[0], 0.0f);
    }
    __syncthreads();
    if (tid < CC) {
        float accv = bconv[tid];
        for (int n = 0; n < NN; n++) accv += xsb[n] * Wconv[tid * NN + n];
        out[(size_t)b * CC + tid] = accv;
    }
    __syncthreads();
}

// ---------------------------------------------------------------------------
// fused kernel: grid 2048, block 128, TB=2 batches/block, 8 blocks/SM.
// Warp w: FMA role = k-quarter w; streams batch bb=w>>1, row-half hh=w&1
// (rows hh*15..hh*15+14). Lane: features f = 4*lane. smem slot index == w.
// ---------------------------------------------------------------------------
__global__ void __launch_bounds__(128, 8) fused_gcn(
    const float* __restrict__ real, const float* __restrict__ graph,
    const float* __restrict__ W1, const float* __restrict__ b1,
    const float* __restrict__ W2, const float* __restrict__ b2,
    const float* __restrict__ Wlin, const float* __restrict__ blin,
    const float* __restrict__ Wconv, const float* __restrict__ bconv,
    float* __restrict__ out)
{
    // buf (10240 B, time-multiplexed):
    //   ubuf0 [128][SB] @ 0    (3072 B) | red64 layer1 [4 q][2 b][128 f] u64
    //   ubuf1 [128][SB] @ 3072 (3072 B) |   @ 0 (8192 B; after chunk loop)
    //   h1T   [128][4]  @ 8192 (2048 B)   (disjoint from layer-2 red64 4 KB)
    __shared__ __align__(16) char buf[10240];
    __shared__ float xp[4][TB];
    __shared__ float xs[TB];
    __shared__ float wsum[CC];
    __shared__ int   flagS[TB];

    float* ub0   = (float*)buf;
    float* ub1   = (float*)(buf + 3072);
    u64t*  red64 = (u64t*)buf;
    float* h1T   = (float*)(buf + 8192);

    const int tid  = threadIdx.x;
    const int b0   = blockIdx.x * TB;
    const int w    = tid >> 5;          // warp 0..3
    const int lane = tid & 31;
    const int f4   = lane * 4;
    const int bb_  = w >> 1;            // streamed batch
    const int hh   = w & 1;             // row half (15 rows each)
    const bool flags_early = ((blockIdx.x & 1) == 0);

    if (tid < TB) flagS[tid] = 1;
    if (tid < CC) {
        float a = 0.f;
        #pragma unroll
        for (int n = 0; n < NN; n++) a += Wconv[tid * NN + n];
        wsum[tid] = a;
    }
    __syncthreads();

    // ---- flags: even blocks now, odd blocks after layer-2 (stagger)
    if (flags_early)
        flags_check(b0, tid, graph, flagS);

    // ---- layer-1 pipeline over 4 K-chunks of 128.
    const float4* rbB = (const float4*)(real + (size_t)(b0 + bb_) * NN * IN_C);
    const float4* rb4 = rbB + (size_t)(hh * 15) * (IN_C / 4);   // my row half

    // prologue: partial colsum (15 rows) of chunk 0 -> ub0 slot w
    {
        float4 a = make_float4(0.f, 0.f, 0.f, 0.f);
        #pragma unroll 5
        for (int r = 0; r < 15; r++) {
            float4 v = rb4[r * (IN_C / 4) + lane];
            a.x += v.x; a.y += v.y; a.z += v.z; a.w += v.w;
        }
        int kb = lane * 4;
        ub0[(kb + 0) * SB + w] = a.x;
        ub0[(kb + 1) * SB + w] = a.y;
        ub0[(kb + 2) * SB + w] = a.z;
        ub0[(kb + 3) * SB + w] = a.w;
    }
    __syncthreads();

    // acc[p][j]: p=0 -> batch0 (h0,h1 packed), p=1 -> batch1 (h0,h1 packed)
    u64t acc[2][4];
    #pragma unroll
    for (int p = 0; p < 2; p++)
        #pragma unroll
        for (int j = 0; j < 4; j++) acc[p][j] = 0ull;

    for (int c = 0; c < 4; c++) {
        float* ub = (c & 1) ? ub1 : ub0;
        float* un = (c & 1) ? ub0 : ub1;
        const bool more = (c < 3);
        const float4* nxt = rb4 + (c + 1) * 32 + lane;    // my rows, next chunk
        float4 a = make_float4(0.f, 0.f, 0.f, 0.f);
        const int kbeg = w * 32;                          // k-quarter in chunk
        const float4* Wp = (const float4*)(W1 + (size_t)(c * 128 + kbeg) * FF) + lane;
        float4 wpf[2];
        wpf[0] = Wp[0];
        wpf[1] = Wp[FF / 4];

        // depth-4 ring on streamed loads: slot ki&3 holds row ki (of 15).
        float4 vr[4];
        if (more) {
            #pragma unroll
            for (int s = 0; s < 4; s++) vr[s] = nxt[s * (IN_C / 4)];
        }
        #pragma unroll
        for (int ki = 0; ki < 32; ki++) {
            float4 v;
            bool cons = more && (ki < 15);
            if (cons) v = vr[ki & 3];
            if (more && (ki + 4 < 15))
                vr[ki & 3] = nxt[(ki + 4) * (IN_C / 4)];
            float4 wv = wpf[ki & 1];
            if (ki + 2 < 32) wpf[ki & 1] = Wp[(ki + 2) * (FF / 4)];
            const float* up = &ub[(kbeg + ki) * SB];
            u64t u0 = *(const u64t*)(up + 0);   // batch0: (h0,h1)
            u64t u1 = *(const u64t*)(up + 2);   // batch1: (h0,h1)
            u64t w0 = pk2(wv.x, wv.x), w1 = pk2(wv.y, wv.y);
            u64t w2 = pk2(wv.z, wv.z), w3 = pk2(wv.w, wv.w);
            fma2(acc[0][0], u0, w0); fma2(acc[1][0], u1, w0);
            fma2(acc[0][1], u0, w1); fma2(acc[1][1], u1, w1);
            fma2(acc[0][2], u0, w2); fma2(acc[1][2], u1, w2);
            fma2(acc[0][3], u0, w3); fma2(acc[1][3], u1, w3);
            if (cons) { a.x += v.x; a.y += v.y; a.z += v.z; a.w += v.w; }
        }
        // write next-chunk partial colsum (slot w): safe — un's last readers
        // finished before the barrier that ended chunk c-1.
        if (more) {
            int kb = lane * 4;
            un[(kb + 0) * SB + w] = a.x;
            un[(kb + 1) * SB + w] = a.y;
            un[(kb + 2) * SB + w] = a.z;
            un[(kb + 3) * SB + w] = a.w;
        }
        __syncthreads();
    }

    // ---- stash layer-1 partials (red64 aliases the dead ubuf region)
    #pragma unroll
    for (int p = 0; p < 2; p++)
        #pragma unroll
        for (int j = 0; j < 4; j++)
            red64[w * 256 + p * 128 + f4 + j] = acc[p][j];
    __syncthreads();

    // ---- reduce q + halves -> h1T[f][b]. Thread tid = feature f.
    {
        const float s1 = 1.0f / 30.0f;
        float bbias = b1[tid];
        #pragma unroll
        for (int b = 0; b < TB; b++) {
            float v = 0.f;
            #pragma unroll
            for (int q = 0; q < 4; q++) {
                float lo, hi; upk2(lo, hi, red64[q * 256 + b * 128 + tid]);
                v += lo + hi;                 // h0 + h1 combine (linear)
            }
            h1T[tid * 4 + b] = fmaxf(fmaf(s1, v, bbias), 0.0f);
        }
    }
    __syncthreads();

    // ---- layer-2 partials. Warp w: k in [32w, 32w+32), both batches packed.
    u64t a2[4];
    #pragma unroll
    for (int j = 0; j < 4; j++) a2[j] = 0ull;
    {
        const int kbeg = w * 32;
        const float4* Wp = (const float4*)(W2 + (size_t)kbeg * FF) + lane;
        float4 wpf[2];
        wpf[0] = Wp[0];
        wpf[1] = Wp[FF / 4];
        #pragma unroll 4
        for (int ki = 0; ki < 32; ki++) {
            float4 wv = wpf[ki & 1];
            int kn = (ki + 2 < 32) ? (ki + 2) : ki;
            wpf[ki & 1] = Wp[kn * (FF / 4)];
            u64t u0 = *(const u64t*)&h1T[(kbeg + ki) * 4];   // (b0, b1)
            u64t w0 = pk2(wv.x, wv.x), w1 = pk2(wv.y, wv.y);
            u64t w2 = pk2(wv.z, wv.z), w3 = pk2(wv.w, wv.w);
            fma2(a2[0], u0, w0);
            fma2(a2[1], u0, w1);
            fma2(a2[2], u0, w2);
            fma2(a2[3], u0, w3);
        }
    }
    // layer-2 red64 (4 KB @ 0) disjoint from h1T (@8192): no barrier needed.
    #pragma unroll
    for (int j = 0; j < 4; j++)
        red64[w * 128 + f4 + j] = a2[j];

    // ---- flags for odd blocks: streams DRAM during others' compute tails.
    if (!flags_early)
        flags_check(b0, tid, graph, flagS);
    __syncthreads();

    // ---- final reduce + epilogue. Thread tid = feature f.
    {
        float bbias = b2[tid];
        float wl = Wlin[tid];
        float sb0 = 0.f, sb1 = 0.f;
        #pragma unroll
        for (int q = 0; q < 4; q++) {
            float lo, hi; upk2(lo, hi, red64[q * 128 + tid]);
            sb0 += lo; sb1 += hi;
        }
        float part[TB];
        part[0] = fmaxf(sb0 + bbias, 0.0f) * wl;
        part[1] = fmaxf(sb1 + bbias, 0.0f) * wl;
        #pragma unroll
        for (int off = 16; off > 0; off >>= 1)
            #pragma unroll
            for (int s = 0; s < TB; s++)
                part[s] += __shfl_xor_sync(0xffffffffu, part[s], off);
        if (lane == 0) {
            xp[w][0] = part[0]; xp[w][1] = part[1];
        }
    }
    __syncthreads();
    if (tid < TB) {
        float s = xp[0][tid] + xp[1][tid] + xp[2][tid] + xp[3][tid];
        xs[tid] = fmaxf(s + blin[0], 0.0f);
    }
    __syncthreads();

    if (tid < TB * CC) {
        int b = tid / CC, c = tid - b * CC;
        if (flagS[b])
            out[(size_t)(b0 + b) * CC + c] = xs[b] * wsum[c] + bconv[c];
    }
    __syncthreads();

    // ---- honest fallback for any non-dense batch (uniform branch)
    for (int fb = 0; fb < TB; fb++) {
        if (!flagS[fb]) {
            fallback_batch(b0 + fb, g_fbscratch[blockIdx.x], tid, real, graph,
                           W1, b1, W2, b2, Wlin, blin, Wconv, bconv, out);
        }
    }
}

// ---------------------------------------------------------------------------
extern "C" void kernel_launch(void* const* d_in, const int* in_sizes, int n_in,
                              void* d_out, int out_size)
{
    const float* real  = (const float*)d_in[0];
    const float* graph = (const float*)d_in[2];
    const float* W1    = (const float*)d_in[3];
    const float* b1    = (const float*)d_in[4];
    const float* W2    = (const float*)d_in[5];
    const float* b2    = (const float*)d_in[6];
    const float* Wlin  = (const float*)d_in[7];
    const float* blin  = (const float*)d_in[8];
    const float* Wconv = (const float*)d_in[9];
    const float* bconv = (const float*)d_in[10];
    float* out = (float*)d_out;

    fused_gcn<<<B_TOT / TB, 128>>>(real, graph, W1, b1, W2, b2, Wlin, blin,
                                   Wconv, bconv, out);
}